// round 6
// baseline (speedup 1.0000x reference)
#include <cuda_runtime.h>

#define NN     10000
#define EE     320000
#define FINN   5
#define FOUT   64
#define MLPH   32
#define CC     27
#define HIDD   450
#define FINAL  128
#define SDIM   168
#define VLEN   (NN*CC)
#define DEGCAP 96

static __device__ int    g_deg[NN];
static __device__ int    g_off[NN + 1];
static __device__ int    g_rank[EE];
static __device__ int    g_esrc[EE];
static __device__ float2 g_eea[EE];
static __device__ float  g_S[NN * SDIM];
static __device__ float  g_xl[NN * CC];
static __device__ float  g_asrc[NN];
static __device__ float  g_adst[NN];
static __device__ int    g_nnz;
static __device__ int    g_cidx[VLEN];
static __device__ float  g_cval[VLEN];
static __device__ float  g_hid[HIDD];

__global__ void k_init() {
    int i = blockIdx.x * blockDim.x + threadIdx.x;
    if (i < NN) g_deg[i] = 0;
    if (i < HIDD) g_hid[i] = 0.f;
    if (i == 0) g_nnz = 0;
}

__global__ void k_hist(const int* __restrict__ ei) {
    int e = blockIdx.x * blockDim.x + threadIdx.x;
    if (e < EE) g_rank[e] = atomicAdd(&g_deg[__ldg(&ei[EE + e])], 1);
}

__global__ void k_scan() {
    const int PER = 40;
    int tid = threadIdx.x;
    int start = tid * PER;
    int local = 0;
    for (int i = 0; i < PER; i++) {
        int idx = start + i;
        if (idx < NN) local += g_deg[idx];
    }
    int lane = tid & 31, w = tid >> 5;
    int incl = local;
    for (int s = 1; s < 32; s <<= 1) {
        int t = __shfl_up_sync(0xffffffffu, incl, s);
        if (lane >= s) incl += t;
    }
    __shared__ int wsum[8];
    __shared__ int woff[8];
    if (lane == 31) wsum[w] = incl;
    __syncthreads();
    if (tid == 0) {
        int c = 0;
        for (int i = 0; i < 8; i++) { woff[i] = c; c += wsum[i]; }
    }
    __syncthreads();
    int run = incl - local + woff[w];
    for (int i = 0; i < PER; i++) {
        int idx = start + i;
        if (idx < NN) { g_off[idx] = run; run += g_deg[idx]; }
    }
    if (tid == 0) g_off[NN] = EE;
}

__global__ void k_scatter(const int* __restrict__ ei, const float* __restrict__ ea) {
    int e = blockIdx.x * blockDim.x + threadIdx.x;
    if (e >= EE) return;
    int dst = __ldg(&ei[EE + e]);
    int slot = g_off[dst] + g_rank[e];
    g_esrc[slot] = __ldg(&ei[e]);
    g_eea[slot] = __ldg((const float2*)ea + e);
}

__global__ void k_S(const float* __restrict__ x, const float* __restrict__ w1,
                    const float* __restrict__ b1) {
    __shared__ float w1s[2 * MLPH];
    __shared__ float b1s[MLPH];
    int tid = threadIdx.x;
    if (tid < 2 * MLPH) w1s[tid] = w1[tid];
    if (tid < MLPH)     b1s[tid] = b1[tid];
    __syncthreads();

    int n = blockIdx.x * 8 + (tid >> 5);
    int j = tid & 31;
    float wa = w1s[j], wb = w1s[MLPH + j], bb = b1s[j];

    float s0 = 0.f, s1 = 0.f, s2 = 0.f, s3 = 0.f, s4 = 0.f, xs = 0.f;
    int k0 = g_off[n], k1 = g_off[n + 1];
#pragma unroll 2
    for (int k = k0; k < k1; k++) {
        int src = __ldg(&g_esrc[k]);
        float2 eav = __ldg(&g_eea[k]);
        float h = fmaxf(fmaf(eav.x, wa, fmaf(eav.y, wb, bb)), 0.f);
        const float* xp = x + src * FINN;
        float x0 = __ldg(xp), x1v = __ldg(xp + 1), x2v = __ldg(xp + 2),
              x3v = __ldg(xp + 3), x4v = __ldg(xp + 4);
        s0 = fmaf(h, x0, s0); s1 = fmaf(h, x1v, s1); s2 = fmaf(h, x2v, s2);
        s3 = fmaf(h, x3v, s3); s4 = fmaf(h, x4v, s4);
        if (j < FINN) {
            float xv = (j == 0) ? x0 : (j == 1) ? x1v : (j == 2) ? x2v : (j == 3) ? x3v : x4v;
            xs += xv;
        }
    }
    float* Sp = g_S + n * SDIM + j * 5;
    Sp[0] = s0; Sp[1] = s1; Sp[2] = s2; Sp[3] = s3; Sp[4] = s4;
    if (j < FINN) g_S[n * SDIM + 160 + j] = xs;
}

__global__ void k_x1xl(const float* __restrict__ x, const float* __restrict__ w2,
                       const float* __restrict__ b2, const float* __restrict__ root,
                       const float* __restrict__ nbias, const float* __restrict__ gw,
                       const float* __restrict__ asv, const float* __restrict__ adv) {
    __shared__ float x1s[8][FOUT];
    int w = threadIdx.x >> 5, lane = threadIdx.x & 31;
    int n = blockIdx.x * 8 + w;
    if (n >= NN) return;
    const float* Sp = g_S + n * SDIM;
    int o0 = lane, o1 = lane + 32;

    float acc0 = __ldg(&nbias[o0]);
    float acc1 = __ldg(&nbias[o1]);
    const float* xp = x + n * FINN;
#pragma unroll
    for (int i = 0; i < FINN; i++) {
        float xi = __ldg(xp + i);
        acc0 = fmaf(xi, __ldg(&root[i * FOUT + o0]), acc0);
        acc1 = fmaf(xi, __ldg(&root[i * FOUT + o1]), acc1);
    }
#pragma unroll 4
    for (int j = 0; j < MLPH; j++) {
#pragma unroll
        for (int i = 0; i < FINN; i++) {
            float sv = Sp[j * 5 + i];
            acc0 = fmaf(sv, __ldg(&w2[j * 320 + i * 64 + o0]), acc0);
            acc1 = fmaf(sv, __ldg(&w2[j * 320 + i * 64 + o1]), acc1);
        }
    }
#pragma unroll
    for (int i = 0; i < FINN; i++) {
        float sv = Sp[160 + i];
        acc0 = fmaf(sv, __ldg(&b2[i * 64 + o0]), acc0);
        acc1 = fmaf(sv, __ldg(&b2[i * 64 + o1]), acc1);
    }
    x1s[w][o0] = fmaxf(acc0, 0.f);
    x1s[w][o1] = fmaxf(acc1, 0.f);
    __syncwarp();

    int c = lane;
    float acc = 0.f;
    if (c < CC) {
#pragma unroll 8
        for (int o = 0; o < FOUT; o++)
            acc = fmaf(x1s[w][o], __ldg(&gw[o * CC + c]), acc);
        g_xl[n * CC + c] = acc;
    }
    float vs = (c < CC) ? acc * __ldg(&asv[c]) : 0.f;
    float vd = (c < CC) ? acc * __ldg(&adv[c]) : 0.f;
    for (int s = 16; s; s >>= 1) {
        vs += __shfl_xor_sync(0xffffffffu, vs, s);
        vd += __shfl_xor_sync(0xffffffffu, vd, s);
    }
    if (lane == 0) { g_asrc[n] = vs; g_adst[n] = vd; }
}

__device__ __forceinline__ float lrelu(float a) { return a > 0.f ? a : 0.2f * a; }

__global__ void k_gat(const float* __restrict__ gbias) {
    __shared__ float abuf[8][DEGCAP];
    __shared__ int   sbuf[8][DEGCAP];
    int w = threadIdx.x >> 5, lane = threadIdx.x & 31;
    int n = blockIdx.x * 8 + w;
    int k0 = g_off[n], k1 = g_off[n + 1];
    int deg = k1 - k0;
    bool fits = (deg <= DEGCAP);
    float ad = g_adst[n];
    float aself = lrelu(g_asrc[n] + ad);

    float m = -1e30f, d = 0.f;
    for (int k = k0 + lane; k < k1; k += 32) {
        int s = __ldg(&g_esrc[k]);
        float a = lrelu(__ldg(&g_asrc[s]) + ad);
        if (fits) { abuf[w][k - k0] = a; sbuf[w][k - k0] = s; }
        float mn = fmaxf(m, a);
        d = fmaf(d, __expf(m - mn), __expf(a - mn));
        m = mn;
    }
    for (int s = 16; s; s >>= 1) {
        float m2 = __shfl_xor_sync(0xffffffffu, m, s);
        float d2 = __shfl_xor_sync(0xffffffffu, d, s);
        float mn = fmaxf(m, m2);
        d = fmaf(d, __expf(m - mn), d2 * __expf(m2 - mn));
        m = mn;
    }
    {
        float mn = fmaxf(m, aself);
        d = fmaf(d, __expf(m - mn), __expf(aself - mn));
        m = mn;
    }
    float inv = 1.f / d;

    int c = lane;
    float out = (c < CC) ? __expf(aself - m) * inv * __ldg(&g_xl[n * CC + c]) : 0.f;
    __syncwarp();

    if (fits) {
#pragma unroll 4
        for (int i = 0; i < deg; i++) {
            float wv = __expf(abuf[w][i] - m) * inv;
            int si = sbuf[w][i];
            if (c < CC) out = fmaf(wv, __ldg(&g_xl[si * CC + c]), out);
        }
    } else {
        for (int k = k0; k < k1; k++) {
            int s = __ldg(&g_esrc[k]);
            float wv = __expf(lrelu(__ldg(&g_asrc[s]) + ad) - m) * inv;
            if (c < CC) out = fmaf(wv, __ldg(&g_xl[s * CC + c]), out);
        }
    }

    float r = 0.f;
    bool pred = false;
    if (c < CC) {
        r = out + __ldg(&gbias[c]);
        pred = (r > 0.f);
    }
    unsigned mask = __ballot_sync(0xffffffffu, pred);
    int cnt = __popc(mask);
    if (cnt) {
        int leader = __ffs(mask) - 1;
        int base = 0;
        if (lane == leader) base = atomicAdd(&g_nnz, cnt);
        base = __shfl_sync(0xffffffffu, base, leader);
        if (pred) {
            int off = __popc(mask & ((1u << lane) - 1));
            g_cidx[base + off] = n * CC + c;
            g_cval[base + off] = r;
        }
    }
}

// fc1: compacted rows, float2 columns (rows are 1800 B = 8B-aligned; float4
// would trap on odd rows), 8-row unroll for deep MLP.
__global__ void k_fc1(const float* __restrict__ w) {
    int t = threadIdx.x;
    if (t >= 225) return;                 // 225 float2 = 450 columns
    int nnz = g_nnz;
    int per = (nnz + gridDim.x - 1) / gridDim.x;
    int i0 = blockIdx.x * per;
    int i1 = i0 + per; if (i1 > nnz) i1 = nnz;
    float ax = 0.f, ay = 0.f;
    int i = i0;
    for (; i + 8 <= i1; i += 8) {
#pragma unroll
        for (int u = 0; u < 8; u++) {
            int r = __ldg(&g_cidx[i + u]);
            float v = __ldg(&g_cval[i + u]);
            float2 b = __ldg((const float2*)(w + (size_t)r * HIDD) + t);
            ax = fmaf(v, b.x, ax); ay = fmaf(v, b.y, ay);
        }
    }
    for (; i < i1; i++) {
        int r = __ldg(&g_cidx[i]);
        float v = __ldg(&g_cval[i]);
        float2 b = __ldg((const float2*)(w + (size_t)r * HIDD) + t);
        ax = fmaf(v, b.x, ax); ay = fmaf(v, b.y, ay);
    }
    atomicAdd(&g_hid[2 * t], ax);
    atomicAdd(&g_hid[2 * t + 1], ay);
}

__global__ void k_fc2out(const float* __restrict__ b1v, const float* __restrict__ w2,
                         const float* __restrict__ b2v, float* __restrict__ out) {
    __shared__ float hs[HIDD];
    int t = threadIdx.x;
    for (int i = t; i < HIDD; i += 256) {
        float h = g_hid[i] + __ldg(&b1v[i]);
        hs[i] = h > 0.f ? h : 0.f;
    }
    __syncthreads();
    if (t < FINAL) {
        float a0 = 0.f, a1 = 0.f;
        // HIDD = 450 is even: the pair loop covers ALL rows; no odd tail.
#pragma unroll 5
        for (int h = 0; h < HIDD; h += 2) {
            a0 = fmaf(hs[h],     __ldg(&w2[h * FINAL + t]),       a0);
            a1 = fmaf(hs[h + 1], __ldg(&w2[(h + 1) * FINAL + t]), a1);
        }
        float v = a0 + a1 + __ldg(&b2v[t]);
        out[t] = v > 0.f ? v : 0.f;
    }
}

extern "C" void kernel_launch(void* const* d_in, const int* in_sizes, int n_in,
                              void* d_out, int out_size) {
    const float* x        = (const float*)d_in[0];
    const int*   ei       = (const int*)  d_in[1];
    const float* ea       = (const float*)d_in[2];
    const float* mlp_w1   = (const float*)d_in[3];
    const float* mlp_b1   = (const float*)d_in[4];
    const float* mlp_w2   = (const float*)d_in[5];
    const float* mlp_b2   = (const float*)d_in[6];
    const float* nn_root  = (const float*)d_in[7];
    const float* nn_bias  = (const float*)d_in[8];
    const float* gat_w    = (const float*)d_in[9];
    const float* att_src  = (const float*)d_in[10];
    const float* att_dst  = (const float*)d_in[11];
    const float* gat_bias = (const float*)d_in[12];
    const float* fc1_w    = (const float*)d_in[13];
    const float* fc1_b    = (const float*)d_in[14];
    const float* fc2_w    = (const float*)d_in[15];
    const float* fc2_b    = (const float*)d_in[16];
    float* out = (float*)d_out;

    k_init<<<(NN + 255) / 256, 256>>>();
    k_hist<<<(EE + 255) / 256, 256>>>(ei);
    k_scan<<<1, 256>>>();
    k_scatter<<<(EE + 255) / 256, 256>>>(ei, ea);
    k_S<<<NN / 8, 256>>>(x, mlp_w1, mlp_b1);
    k_x1xl<<<NN / 8, 256>>>(x, mlp_w2, mlp_b2, nn_root, nn_bias,
                            gat_w, att_src, att_dst);
    k_gat<<<NN / 8, 256>>>(gat_bias);
    k_fc1<<<2048, 256>>>(fc1_w);
    k_fc2out<<<1, 256>>>(fc1_b, fc2_w, fc2_b, out);
}